// round 8
// baseline (speedup 1.0000x reference)
#include <cuda_runtime.h>

// Problem constants
#define NB   8
#define CCH  20
#define HH_  64
#define WW_  2048

// Tiling
#define HT   4            // output rows per block
#define WT   128          // output cols per block
#define HT2  8            // HT + 4 (halo of 2 each side)
#define WVAL 132          // WT + 4 valid cols
#define WSTR 136          // padded row stride (floats), 544 B = 16B-aligned rows

// smem layout (floats)
#define OFF_XYZ   0
#define OFF_MASK  (3 * HT2 * WSTR)
#define OFF_SM    (OFF_MASK + HT2 * WSTR)
#define SMEM_FLOATS (OFF_SM + CCH * HT2 * WSTR)
#define SMEM_BYTES  (SMEM_FLOATS * 4)              // 104448

// ---------------- mask dtype detection ----------------
// g_flags[0]: some 32-bit word not in {0,1}          -> not int32 0/1
// g_flags[1]: some 32-bit word not in {0,0x3F800000} -> not float32 0/1
__device__ unsigned int g_flags[2];

__global__ void mask_reset_kernel() {
    g_flags[0] = 0u;
    g_flags[1] = 0u;
}

// Scan only the guaranteed-minimum buffer size: mask has 1,048,576 elements;
// worst case (uint8) the buffer is 1,048,576 bytes = 262,144 words.
#define MASK_WORDS (NB * HH_ * WW_ / 4)

__global__ void mask_detect_kernel(const unsigned int* __restrict__ m) {
    unsigned int a = 0, b = 0;
    for (int i = blockIdx.x * blockDim.x + threadIdx.x; i < MASK_WORDS;
         i += gridDim.x * blockDim.x) {
        unsigned int v = m[i];
        a |= (unsigned int)(v != 0u && v != 1u);
        b |= (unsigned int)(v != 0u && v != 0x3F800000u);
    }
    if (a) atomicOr(&g_flags[0], 1u);
    if (b) atomicOr(&g_flags[1], 1u);
}

__device__ __forceinline__ float load_mask(const void* mask, int idx,
                                           unsigned int f0, unsigned int f1) {
    if (!f0)  return (float)((const int*)mask)[idx];            // int32 0/1
    if (!f1)  return ((const float*)mask)[idx];                 // float32 0/1
    return (float)((const unsigned char*)mask)[idx];            // uint8/bool
}

// ---------------- main kernel ----------------
__global__ __launch_bounds__(128)
void lcxyz_kernel(const float* __restrict__ xyz,
                  const float* __restrict__ softmax,
                  const void*  __restrict__ mask,
                  float* __restrict__ out)
{
    extern __shared__ float smem[];
    float* s_xyz  = smem + OFF_XYZ;   // [3][HT2][WSTR]
    float* s_mask = smem + OFF_MASK;  // [HT2][WSTR]
    float* s_sm   = smem + OFF_SM;    // [CCH][HT2][WSTR]

    const int tid = threadIdx.x;
    const int n   = blockIdx.z;
    const int h0  = blockIdx.y * HT;
    const int w0  = blockIdx.x * WT;

    const unsigned int f0 = g_flags[0];
    const unsigned int f1 = g_flags[1];

    // ---- Phase 1: stage xyz (torus wrap) and mask (zero pad) ----
    for (int i = tid; i < 3 * HT2 * WVAL; i += 128) {
        int ch  = i / (HT2 * WVAL);
        int rem = i - ch * (HT2 * WVAL);
        int r   = rem / WVAL;
        int idx = rem - r * WVAL;
        int hh  = (h0 + r - 2 + HH_) & (HH_ - 1);
        int ww  = (w0 + idx - 2 + WW_) & (WW_ - 1);
        s_xyz[(ch * HT2 + r) * WSTR + idx] =
            xyz[((n * 3 + ch) * HH_ + hh) * WW_ + ww];
    }
    for (int i = tid; i < HT2 * WVAL; i += 128) {
        int r   = i / WVAL;
        int idx = i - r * WVAL;
        int hh  = h0 + r - 2;
        int ww  = w0 + idx - 2;
        float m = 0.0f;
        if (hh >= 0 && hh < HH_ && ww >= 0 && ww < WW_)
            m = load_mask(mask, (n * HH_ + hh) * WW_ + ww, f0, f1);
        s_mask[r * WSTR + idx] = m;
    }
    __syncthreads();

    // ---- Phase 2: stage masked softmax (zero pad) ----
    for (int i = tid; i < CCH * HT2 * WVAL; i += 128) {
        int c   = i / (HT2 * WVAL);
        int rem = i - c * (HT2 * WVAL);
        int r   = rem / WVAL;
        int idx = rem - r * WVAL;
        int hh  = h0 + r - 2;
        int ww  = w0 + idx - 2;
        float v = 0.0f;
        if (hh >= 0 && hh < HH_ && ww >= 0 && ww < WW_)
            v = softmax[((n * CCH + c) * HH_ + hh) * WW_ + ww] *
                s_mask[r * WSTR + idx];
        s_sm[(c * HT2 + r) * WSTR + idx] = v;
    }
    __syncthreads();

    // ---- Phase 3: compute. Thread (tx,ty): 4 outputs at (h0+ty, w0+4*tx..+3) ----
    const int tx = tid & 31;
    const int ty = tid >> 5;
    const int wl = tx << 2;   // local col base; smem phys index of global col c is c-w0+2

    // center xyz (row ty+2, phys cols wl+2..wl+5)
    float xc0[4], xc1[4], xc2[4];
    #pragma unroll
    for (int o = 0; o < 4; ++o) {
        xc0[o] = s_xyz[(0 * HT2 + ty + 2) * WSTR + wl + o + 2];
        xc1[o] = s_xyz[(1 * HT2 + ty + 2) * WSTR + wl + o + 2];
        xc2[o] = s_xyz[(2 * HT2 + ty + 2) * WSTR + wl + o + 2];
    }

    float acc[CCH][4];
    #pragma unroll
    for (int c = 0; c < CCH; ++c)
        #pragma unroll
        for (int o = 0; o < 4; ++o) acc[c][o] = 0.0f;

    #pragma unroll 1
    for (int di = 0; di < 5; ++di) {
        const int r = ty + di;

        // xyz window: phys cols wl..wl+7 (16B aligned) for 3 channels
        float xv0[8], xv1[8], xv2[8];
        {
            const float4* p = (const float4*)&s_xyz[(0 * HT2 + r) * WSTR + wl];
            float4 a = p[0], b = p[1];
            xv0[0]=a.x; xv0[1]=a.y; xv0[2]=a.z; xv0[3]=a.w;
            xv0[4]=b.x; xv0[5]=b.y; xv0[6]=b.z; xv0[7]=b.w;
        }
        {
            const float4* p = (const float4*)&s_xyz[(1 * HT2 + r) * WSTR + wl];
            float4 a = p[0], b = p[1];
            xv1[0]=a.x; xv1[1]=a.y; xv1[2]=a.z; xv1[3]=a.w;
            xv1[4]=b.x; xv1[5]=b.y; xv1[6]=b.z; xv1[7]=b.w;
        }
        {
            const float4* p = (const float4*)&s_xyz[(2 * HT2 + r) * WSTR + wl];
            float4 a = p[0], b = p[1];
            xv2[0]=a.x; xv2[1]=a.y; xv2[2]=a.z; xv2[3]=a.w;
            xv2[4]=b.x; xv2[5]=b.y; xv2[6]=b.z; xv2[7]=b.w;
        }

        // 20 weights for this di (4 outputs x 5 dj): wgt = exp(-d2/2)
        float wgt[4][5];
        #pragma unroll
        for (int dj = 0; dj < 5; ++dj) {
            #pragma unroll
            for (int o = 0; o < 4; ++o) {
                float dx = xv0[o + dj] - xc0[o];
                float dy = xv1[o + dj] - xc1[o];
                float dz = xv2[o + dj] - xc2[o];
                float d2 = dx * dx + dy * dy + dz * dz;
                wgt[o][dj] = __expf(-0.5f * d2);
            }
        }

        // accumulate all 20 channels: 2 x LDS.128 + 20 FMA per channel
        #pragma unroll
        for (int c = 0; c < CCH; ++c) {
            const float4* p = (const float4*)&s_sm[(c * HT2 + r) * WSTR + wl];
            float4 a = p[0], b = p[1];
            float s[8];
            s[0]=a.x; s[1]=a.y; s[2]=a.z; s[3]=a.w;
            s[4]=b.x; s[5]=b.y; s[6]=b.z; s[7]=b.w;
            #pragma unroll
            for (int o = 0; o < 4; ++o) {
                #pragma unroll
                for (int dj = 0; dj < 5; ++dj)
                    acc[c][o] += wgt[o][dj] * s[o + dj];
            }
        }
    }

    // ---- store: float4 per channel ----
    const int gh = h0 + ty;
    const int gw = w0 + wl;
    #pragma unroll
    for (int c = 0; c < CCH; ++c) {
        float4 v = make_float4(acc[c][0], acc[c][1], acc[c][2], acc[c][3]);
        *(float4*)&out[((n * CCH + c) * HH_ + gh) * WW_ + gw] = v;
    }
}

extern "C" void kernel_launch(void* const* d_in, const int* in_sizes, int n_in,
                              void* d_out, int out_size)
{
    const float* xyz  = (const float*)d_in[0];
    const float* sm   = (const float*)d_in[1];
    const void*  mask = d_in[2];
    float*       out  = (float*)d_out;

    (void)in_sizes; (void)n_in; (void)out_size;

    cudaFuncSetAttribute(lcxyz_kernel,
                         cudaFuncAttributeMaxDynamicSharedMemorySize,
                         SMEM_BYTES);

    // 1) reset detection flags, 2) detect mask dtype, 3) main compute.
    mask_reset_kernel<<<1, 1>>>();
    mask_detect_kernel<<<128, 256>>>((const unsigned int*)mask);

    dim3 grid(WW_ / WT, HH_ / HT, NB);   // 16 x 16 x 8 = 2048 blocks
    lcxyz_kernel<<<grid, 128, SMEM_BYTES>>>(xyz, sm, mask, out);
}

// round 9
// speedup vs baseline: 1.3244x; 1.3244x over previous
#include <cuda_runtime.h>

// Problem constants
#define NB   8
#define CCH  20
#define HH_  64
#define WW_  2048

// Tiling: each block does 10 channels x 4 rows x 128 cols
#define CC   10           // channels per block (chunk)
#define HT   4            // output rows per block
#define WT   128          // output cols per block
#define HT2  8            // HT + 4 halo rows
#define WVAL 132          // WT + 4 valid cols
#define WSTR 136          // padded row stride (floats): 544B, 16B-aligned rows

// smem layout (floats)
#define OFF_XYZ   0
#define OFF_MASK  (3 * HT2 * WSTR)                  // 3264
#define OFF_SM    (OFF_MASK + HT2 * WSTR)           // 4352
#define SMEM_FLOATS (OFF_SM + CC * HT2 * WSTR)      // 15232
#define SMEM_BYTES  (SMEM_FLOATS * 4)               // 60928

__global__ __launch_bounds__(128)
void lcxyz_kernel(const float* __restrict__ xyz,
                  const float* __restrict__ softmax,
                  const unsigned int* __restrict__ mask,  // int32 or f32 0/1: word!=0
                  float* __restrict__ out)
{
    extern __shared__ float smem[];
    float* s_xyz  = smem + OFF_XYZ;   // [3][HT2][WSTR]
    float* s_mask = smem + OFF_MASK;  // [HT2][WSTR]
    float* s_sm   = smem + OFF_SM;    // [CC][HT2][WSTR]

    const int tid  = threadIdx.x;
    const int wid  = tid >> 5;
    const int lane = tid & 31;

    const int n    = blockIdx.z >> 1;
    const int c0   = (blockIdx.z & 1) * CC;
    const int h0   = blockIdx.y * HT;
    const int w0   = blockIdx.x * WT;

    // ---- Phase 1a: xyz (torus wrap), 24 (ch,r) rows, one row per warp ----
    #pragma unroll 1
    for (int p = wid; p < 3 * HT2; p += 4) {
        const int ch = p >> 3;
        const int r  = p & 7;
        const int hh = (h0 + r - 2) & (HH_ - 1);
        const float* src = xyz + ((size_t)(n * 3 + ch) * HH_ + hh) * WW_;
        float* dst = s_xyz + p * WSTR;
        #pragma unroll
        for (int idx = lane; idx < WVAL; idx += 32) {
            int ww = (w0 + idx - 2) & (WW_ - 1);
            dst[idx] = src[ww];
        }
    }

    // ---- Phase 1b: mask (zero pad), 8 rows ----
    #pragma unroll 1
    for (int r = wid; r < HT2; r += 4) {
        const int hh = h0 + r - 2;
        const bool hv = (hh >= 0) && (hh < HH_);
        const unsigned int* src = mask + (size_t)(n * HH_ + hh) * WW_;
        float* dst = s_mask + r * WSTR;
        #pragma unroll
        for (int idx = lane; idx < WVAL; idx += 32) {
            int ww = w0 + idx - 2;
            float m = 0.0f;
            if (hv && (unsigned)ww < (unsigned)WW_)
                m = (src[ww] != 0u) ? 1.0f : 0.0f;
            dst[idx] = m;
        }
    }
    __syncthreads();

    // ---- Phase 2: masked softmax (zero pad), 80 (c,r) rows ----
    #pragma unroll 1
    for (int p = wid; p < CC * HT2; p += 4) {
        const int c = p >> 3;
        const int r = p & 7;
        const int hh = h0 + r - 2;
        const bool hv = (hh >= 0) && (hh < HH_);
        const float* src = softmax + ((size_t)(n * CCH + c0 + c) * HH_ + hh) * WW_;
        const float* mrow = s_mask + r * WSTR;
        float* dst = s_sm + p * WSTR;
        #pragma unroll
        for (int idx = lane; idx < WVAL; idx += 32) {
            int ww = w0 + idx - 2;
            float v = 0.0f;
            if (hv && (unsigned)ww < (unsigned)WW_)
                v = src[ww] * mrow[idx];
            dst[idx] = v;
        }
    }
    __syncthreads();

    // ---- Phase 3: compute. Thread (tx,ty): 4 outputs at (h0+ty, w0+4*tx..+3) ----
    const int tx = lane;
    const int ty = wid;
    const int wl = tx << 2;   // smem phys col of output o is wl+o+2

    // center xyz (row ty+2)
    float xc0[4], xc1[4], xc2[4];
    #pragma unroll
    for (int o = 0; o < 4; ++o) {
        xc0[o] = s_xyz[(0 * HT2 + ty + 2) * WSTR + wl + o + 2];
        xc1[o] = s_xyz[(1 * HT2 + ty + 2) * WSTR + wl + o + 2];
        xc2[o] = s_xyz[(2 * HT2 + ty + 2) * WSTR + wl + o + 2];
    }

    float acc[CC][4];
    #pragma unroll
    for (int c = 0; c < CC; ++c)
        #pragma unroll
        for (int o = 0; o < 4; ++o) acc[c][o] = 0.0f;

    #pragma unroll 1
    for (int di = 0; di < 5; ++di) {
        const int r = ty + di;

        // xyz window: phys cols wl..wl+7 (16B aligned), 3 channels
        float xv0[8], xv1[8], xv2[8];
        {
            const float4* p = (const float4*)&s_xyz[(0 * HT2 + r) * WSTR + wl];
            float4 a = p[0], b = p[1];
            xv0[0]=a.x; xv0[1]=a.y; xv0[2]=a.z; xv0[3]=a.w;
            xv0[4]=b.x; xv0[5]=b.y; xv0[6]=b.z; xv0[7]=b.w;
        }
        {
            const float4* p = (const float4*)&s_xyz[(1 * HT2 + r) * WSTR + wl];
            float4 a = p[0], b = p[1];
            xv1[0]=a.x; xv1[1]=a.y; xv1[2]=a.z; xv1[3]=a.w;
            xv1[4]=b.x; xv1[5]=b.y; xv1[6]=b.z; xv1[7]=b.w;
        }
        {
            const float4* p = (const float4*)&s_xyz[(2 * HT2 + r) * WSTR + wl];
            float4 a = p[0], b = p[1];
            xv2[0]=a.x; xv2[1]=a.y; xv2[2]=a.z; xv2[3]=a.w;
            xv2[4]=b.x; xv2[5]=b.y; xv2[6]=b.z; xv2[7]=b.w;
        }

        // 20 weights for this di: wgt[o][dj] = exp(-d2/2)
        float wgt[4][5];
        #pragma unroll
        for (int dj = 0; dj < 5; ++dj) {
            #pragma unroll
            for (int o = 0; o < 4; ++o) {
                float dx = xv0[o + dj] - xc0[o];
                float dy = xv1[o + dj] - xc1[o];
                float dz = xv2[o + dj] - xc2[o];
                float d2 = dx * dx + dy * dy + dz * dz;
                wgt[o][dj] = __expf(-0.5f * d2);
            }
        }

        // accumulate 10 channels: 2 x LDS.128 + 20 FFMA per channel
        #pragma unroll
        for (int c = 0; c < CC; ++c) {
            const float4* p = (const float4*)&s_sm[(c * HT2 + r) * WSTR + wl];
            float4 a = p[0], b = p[1];
            float s[8];
            s[0]=a.x; s[1]=a.y; s[2]=a.z; s[3]=a.w;
            s[4]=b.x; s[5]=b.y; s[6]=b.z; s[7]=b.w;
            #pragma unroll
            for (int o = 0; o < 4; ++o) {
                #pragma unroll
                for (int dj = 0; dj < 5; ++dj)
                    acc[c][o] += wgt[o][dj] * s[o + dj];
            }
        }
    }

    // ---- store: float4 per channel ----
    const int gh = h0 + ty;
    const int gw = w0 + wl;
    #pragma unroll
    for (int c = 0; c < CC; ++c) {
        float4 v = make_float4(acc[c][0], acc[c][1], acc[c][2], acc[c][3]);
        *(float4*)&out[((size_t)(n * CCH + c0 + c) * HH_ + gh) * WW_ + gw] = v;
    }
}

extern "C" void kernel_launch(void* const* d_in, const int* in_sizes, int n_in,
                              void* d_out, int out_size)
{
    const float*        xyz  = (const float*)d_in[0];
    const float*        sm   = (const float*)d_in[1];
    const unsigned int* mask = (const unsigned int*)d_in[2];
    float*              out  = (float*)d_out;

    (void)in_sizes; (void)n_in; (void)out_size;

    cudaFuncSetAttribute(lcxyz_kernel,
                         cudaFuncAttributeMaxDynamicSharedMemorySize,
                         SMEM_BYTES);

    dim3 grid(WW_ / WT, HH_ / HT, NB * 2);   // 16 x 16 x 16 = 4096 blocks
    lcxyz_kernel<<<grid, 128, SMEM_BYTES>>>(xyz, sm, mask, out);
}